// round 3
// baseline (speedup 1.0000x reference)
#include <cuda_runtime.h>

// GMM log-likelihood, N=524288, K=32, D=8. Single fused kernel.
//
// Math: cov = LL^T + eps*I, eps=1e-6. Use L directly instead of chol(cov):
// sign flips leave maha and logdet invariant; eps perturbation ~1e-6 rel.
//
// Per point-k: wll_k = c_k - ||W_k x + t_k||^2 with W = L^{-1} scaled by
// sqrt(0.5*log2(e)) so that exp() becomes a bare ex2.approx (no FMUL),
// c_k pre-scaled by log2(e) and offset by M = max_k c_k so the streaming
// exp-accumulate needs no per-point max. Params live in smem as (k, k+16)
// f32x2 pairs in exact consumption order; main loop is fma.rn.f32x2 only.

typedef unsigned long long u64;

#define DIM 8
#define KP 16          // k-pairs (k, k+16)
#define SLOTS 46       // u64 slots per k-pair (45 used, slot 45 pad)

// ---------------- packed f32x2 helpers ----------------
__device__ __forceinline__ u64 pack2(float a, float b) {
    u64 r; asm("mov.b64 %0, {%1, %2};" : "=l"(r) : "f"(a), "f"(b)); return r;
}
__device__ __forceinline__ void unpack2(u64 v, float& a, float& b) {
    asm("mov.b64 {%0, %1}, %2;" : "=f"(a), "=f"(b) : "l"(v));
}
__device__ __forceinline__ u64 ffma2(u64 a, u64 b, u64 c) {
    u64 d; asm("fma.rn.f32x2 %0, %1, %2, %3;" : "=l"(d) : "l"(a), "l"(b), "l"(c)); return d;
}
__device__ __forceinline__ float ex2f(float x) {
    float r; asm("ex2.approx.f32 %0, %1;" : "=f"(r) : "f"(x)); return r;
}

// slot layout per k-pair (consumption order):
//   for i in 0..7:  t_i  then  W_i0..W_ii     (8 + 36 slots)
//   const at slot 44
__device__ __forceinline__ int slot_t(int i) { return i + (i * (i + 1)) / 2; }
__device__ __forceinline__ int slot_w(int i, int j) { return i + (i * (i + 1)) / 2 + 1 + j; }

__global__ void __launch_bounds__(256, 3)
gmm_fused(const float* __restrict__ x,
          const float* __restrict__ pi,
          const float* __restrict__ means,
          const float* __restrict__ cv,
          float* __restrict__ out, int half) {
    __shared__ __align__(16) u64 sw[KP * SLOTS];
    __shared__ float sM;

    const int tid = threadIdx.x;
    const int gid = blockIdx.x * blockDim.x + tid;

    // issue x loads early; they overlap warp 0's prep work
    const float4* xa4 = reinterpret_cast<const float4*>(x + (size_t)gid * 8);
    const float4* xb4 = reinterpret_cast<const float4*>(x + ((size_t)gid + (size_t)half) * 8);
    float4 a0 = xa4[0], a1 = xa4[1];
    float4 b0 = xb4[0], b1 = xb4[1];

    // ---------------- prep: warp 0, one thread per component ----------------
    if (tid < 32) {
        const int k = tid;
        const int kp = k & (KP - 1);
        const int lane = k >> 4;
        float* swf = reinterpret_cast<float*>(sw);

        // L lower-triangular, packed idx(i,j) = i(i+1)/2 + j
        float L[36];
#pragma unroll
        for (int i = 0; i < DIM; i++)
#pragma unroll
            for (int j = 0; j <= i; j++)
                L[(i * (i + 1)) / 2 + j] = cv[k * 64 + i * 8 + j];

        float Ld[DIM];  // 1/L_ii
#pragma unroll
        for (int i = 0; i < DIM; i++)
            Ld[i] = __fdividef(1.0f, L[(i * (i + 1)) / 2 + i]);

        float mu[DIM];
#pragma unroll
        for (int j = 0; j < DIM; j++) mu[j] = means[k * 8 + j];

        const float LOG2E = 1.4426950408889634f;
        const float s = 0.84932180028801905f;  // sqrt(0.5*log2(e)): folds -0.5 and log2e
        float zm[DIM];
#pragma unroll
        for (int i = 0; i < DIM; i++) zm[i] = 0.0f;

        // triangular inverse, column by column; write scaled entries,
        // accumulate zm_i = sum_j W_ij * mu_j on the fly
#pragma unroll
        for (int c = 0; c < DIM; c++) {
            float g[DIM];
            g[c] = Ld[c];
#pragma unroll
            for (int i = c + 1; i < DIM; i++) {
                float t = 0.0f;
#pragma unroll
                for (int p = c; p < i; p++) t += L[(i * (i + 1)) / 2 + p] * g[p];
                g[i] = -t * Ld[i];
            }
#pragma unroll
            for (int i = c; i < DIM; i++) {
                float wv = g[i] * s;
                swf[(kp * SLOTS + slot_w(i, c)) * 2 + lane] = wv;
                zm[i] += wv * mu[c];
            }
        }
#pragma unroll
        for (int i = 0; i < DIM; i++)
            swf[(kp * SLOTS + slot_t(i)) * 2 + lane] = -zm[i];

        // logdet = 2 * sum log|L_ii|
        float logdet = 0.0f;
#pragma unroll
        for (int i = 0; i < DIM; i++)
            logdet += __logf(fabsf(L[(i * (i + 1)) / 2 + i]));
        logdet *= 2.0f;

        // log_softmax(pi)[k] across the 32 lanes
        float pk = pi[k];
        float mx = pk;
#pragma unroll
        for (int o = 16; o; o >>= 1) mx = fmaxf(mx, __shfl_xor_sync(0xffffffffu, mx, o));
        float se = __expf(pk - mx);
#pragma unroll
        for (int o = 16; o; o >>= 1) se += __shfl_xor_sync(0xffffffffu, se, o);
        float lp = pk - mx - __logf(se);

        const float LOG_2PI = 1.8378770664093453f;
        float cst2 = (lp - 0.5f * (8.0f * LOG_2PI + logdet)) * LOG2E;  // log2 domain

        // M2 = max_k cst2; fold into constant
        float M2 = cst2;
#pragma unroll
        for (int o = 16; o; o >>= 1) M2 = fmaxf(M2, __shfl_xor_sync(0xffffffffu, M2, o));
        swf[(kp * SLOTS + 44) * 2 + lane] = cst2 - M2;
        if (k == 0) sM = M2 * 0.69314718055994531f;  // back to ln domain
    }
    __syncthreads();

    // ---------------- main loop ----------------
    u64 xp[DIM], xq[DIM];
    xp[0] = pack2(a0.x, a0.x); xp[1] = pack2(a0.y, a0.y);
    xp[2] = pack2(a0.z, a0.z); xp[3] = pack2(a0.w, a0.w);
    xp[4] = pack2(a1.x, a1.x); xp[5] = pack2(a1.y, a1.y);
    xp[6] = pack2(a1.z, a1.z); xp[7] = pack2(a1.w, a1.w);
    xq[0] = pack2(b0.x, b0.x); xq[1] = pack2(b0.y, b0.y);
    xq[2] = pack2(b0.z, b0.z); xq[3] = pack2(b0.w, b0.w);
    xq[4] = pack2(b1.x, b1.x); xq[5] = pack2(b1.y, b1.y);
    xq[6] = pack2(b1.z, b1.z); xq[7] = pack2(b1.w, b1.w);

    const u64 negone = pack2(-1.0f, -1.0f);
    float sa0 = 0.f, sa1 = 0.f, sb0 = 0.f, sb1 = 0.f;

#pragma unroll
    for (int kp = 0; kp < KP; kp++) {
        const u64* w = sw + kp * SLOTS;
        u64 qa = 0ull, qb = 0ull;
        int idx = 0;
#pragma unroll
        for (int i = 0; i < DIM; i++) {
            u64 zi = w[idx++];          // -W mu (scaled), packed (k, k+16)
            u64 za = zi, zb = zi;
#pragma unroll
            for (int j = 0; j <= i; j++) {
                u64 p = w[idx++];       // W_ij (scaled), packed (k, k+16)
                za = ffma2(p, xp[j], za);
                zb = ffma2(p, xq[j], zb);
            }
            qa = ffma2(za, za, qa);
            qb = ffma2(zb, zb, qb);
        }
        u64 cc = w[44];                 // (c - M) in log2 domain, packed
        u64 wa = ffma2(qa, negone, cc); // c' - q'
        u64 wb = ffma2(qb, negone, cc);
        float f0, f1;
        unpack2(wa, f0, f1);
        sa0 += ex2f(f0); sa1 += ex2f(f1);
        unpack2(wb, f0, f1);
        sb0 += ex2f(f0); sb1 += ex2f(f1);
    }

    const float M = sM;
    out[gid] = M + __logf(fmaxf(sa0 + sa1, 1e-37f));
    out[gid + (size_t)half] = M + __logf(fmaxf(sb0 + sb1, 1e-37f));
}

extern "C" void kernel_launch(void* const* d_in, const int* in_sizes, int n_in,
                              void* d_out, int out_size) {
    const float* x     = (const float*)d_in[0];
    const float* pi    = (const float*)d_in[1];
    const float* means = (const float*)d_in[2];
    const float* cv    = (const float*)d_in[3];
    float* out = (float*)d_out;

    const int n    = in_sizes[0] / 8;   // 524288
    const int half = n / 2;             // 262144

    gmm_fused<<<half / 256, 256>>>(x, pi, means, cv, out, half);
}

// round 4
// speedup vs baseline: 1.0428x; 1.0428x over previous
#include <cuda_runtime.h>

// GMM log-likelihood, N=524288, K=32, D=8. Single fused kernel.
//
// Round-4 structure: 4 points per thread. This halves the shared-memory
// instruction count (the round-3 kernel was dual-pipe-bound: FFMA2 pipe and
// smem crossbar both at their ~40K-cycle floors and serializing). Each param
// LDS.64 now feeds 4 independent FFMA2 chains; smem pipe drops to ~half the
// FMA floor so the FMA pipe is the sole binder.
//
// Math: cov = LL^T + eps*I, eps=1e-6. Use L directly instead of chol(cov):
// sign flips leave maha and logdet invariant; eps perturbation ~1e-6 rel.
// W = L^{-1} scaled by sqrt(0.5*log2(e)) so exp() is a bare ex2.approx;
// constants pre-scaled by log2(e) and offset by M = max_k c_k.
// Params in smem as (k, k+16) f32x2 pairs in exact consumption order.

typedef unsigned long long u64;

#define DIM 8
#define KP 16          // k-pairs (k, k+16)
#define SLOTS 46       // u64 slots per k-pair (45 used, slot 45 pad)

__device__ __forceinline__ u64 pack2(float a, float b) {
    u64 r; asm("mov.b64 %0, {%1, %2};" : "=l"(r) : "f"(a), "f"(b)); return r;
}
__device__ __forceinline__ void unpack2(u64 v, float& a, float& b) {
    asm("mov.b64 {%0, %1}, %2;" : "=f"(a), "=f"(b) : "l"(v));
}
__device__ __forceinline__ u64 ffma2(u64 a, u64 b, u64 c) {
    u64 d; asm("fma.rn.f32x2 %0, %1, %2, %3;" : "=l"(d) : "l"(a), "l"(b), "l"(c)); return d;
}
__device__ __forceinline__ float ex2f(float x) {
    float r; asm("ex2.approx.f32 %0, %1;" : "=f"(r) : "f"(x)); return r;
}

// slot layout per k-pair (consumption order):
//   for i in 0..7:  t_i  then  W_i0..W_ii     (8 + 36 slots), const at 44
__device__ __forceinline__ int slot_t(int i) { return i + (i * (i + 1)) / 2; }
__device__ __forceinline__ int slot_w(int i, int j) { return i + (i * (i + 1)) / 2 + 1 + j; }

__global__ void __launch_bounds__(128)
gmm_fused(const float* __restrict__ x,
          const float* __restrict__ pi,
          const float* __restrict__ means,
          const float* __restrict__ cv,
          float* __restrict__ out, int q) {
    __shared__ __align__(16) u64 sw[KP * SLOTS];
    __shared__ float sM;

    const int tid = threadIdx.x;
    const int gid = blockIdx.x * blockDim.x + tid;

    // four strided-coalesced points per thread; loads overlap warp 0's prep
    const float4* x4a = reinterpret_cast<const float4*>(x + (size_t)gid * 8);
    const float4* x4b = reinterpret_cast<const float4*>(x + ((size_t)gid + (size_t)q) * 8);
    const float4* x4c = reinterpret_cast<const float4*>(x + ((size_t)gid + 2 * (size_t)q) * 8);
    const float4* x4d = reinterpret_cast<const float4*>(x + ((size_t)gid + 3 * (size_t)q) * 8);
    float4 a0 = x4a[0], a1 = x4a[1];
    float4 b0 = x4b[0], b1 = x4b[1];
    float4 c0 = x4c[0], c1 = x4c[1];
    float4 d0 = x4d[0], d1 = x4d[1];

    // ---------------- prep: warp 0, one thread per component ----------------
    if (tid < 32) {
        const int k = tid;
        const int kp = k & (KP - 1);
        const int lane = k >> 4;
        float* swf = reinterpret_cast<float*>(sw);

        float L[36];
#pragma unroll
        for (int i = 0; i < DIM; i++)
#pragma unroll
            for (int j = 0; j <= i; j++)
                L[(i * (i + 1)) / 2 + j] = cv[k * 64 + i * 8 + j];

        float Ld[DIM];
#pragma unroll
        for (int i = 0; i < DIM; i++)
            Ld[i] = __fdividef(1.0f, L[(i * (i + 1)) / 2 + i]);

        float mu[DIM];
#pragma unroll
        for (int j = 0; j < DIM; j++) mu[j] = means[k * 8 + j];

        const float LOG2E = 1.4426950408889634f;
        const float s = 0.84932180028801905f;  // sqrt(0.5*log2(e))
        float zm[DIM];
#pragma unroll
        for (int i = 0; i < DIM; i++) zm[i] = 0.0f;

        // column-wise triangular inverse, scaled; zm accumulated on the fly
#pragma unroll
        for (int c = 0; c < DIM; c++) {
            float g[DIM];
            g[c] = Ld[c];
#pragma unroll
            for (int i = c + 1; i < DIM; i++) {
                float t = 0.0f;
#pragma unroll
                for (int p = c; p < i; p++) t += L[(i * (i + 1)) / 2 + p] * g[p];
                g[i] = -t * Ld[i];
            }
#pragma unroll
            for (int i = c; i < DIM; i++) {
                float wv = g[i] * s;
                swf[(kp * SLOTS + slot_w(i, c)) * 2 + lane] = wv;
                zm[i] += wv * mu[c];
            }
        }
#pragma unroll
        for (int i = 0; i < DIM; i++)
            swf[(kp * SLOTS + slot_t(i)) * 2 + lane] = -zm[i];

        float logdet = 0.0f;
#pragma unroll
        for (int i = 0; i < DIM; i++)
            logdet += __logf(fabsf(L[(i * (i + 1)) / 2 + i]));
        logdet *= 2.0f;

        // log_softmax(pi)[k]
        float pk = pi[k];
        float mx = pk;
#pragma unroll
        for (int o = 16; o; o >>= 1) mx = fmaxf(mx, __shfl_xor_sync(0xffffffffu, mx, o));
        float se = __expf(pk - mx);
#pragma unroll
        for (int o = 16; o; o >>= 1) se += __shfl_xor_sync(0xffffffffu, se, o);
        float lp = pk - mx - __logf(se);

        const float LOG_2PI = 1.8378770664093453f;
        float cst2 = (lp - 0.5f * (8.0f * LOG_2PI + logdet)) * LOG2E;  // log2 domain

        float M2 = cst2;
#pragma unroll
        for (int o = 16; o; o >>= 1) M2 = fmaxf(M2, __shfl_xor_sync(0xffffffffu, M2, o));
        swf[(kp * SLOTS + 44) * 2 + lane] = cst2 - M2;
        if (k == 0) sM = M2 * 0.69314718055994531f;
    }
    __syncthreads();

    // ---------------- main loop: 4 points, 16 k-pairs ----------------
    u64 xa[DIM], xb[DIM], xc[DIM], xd[DIM];
    xa[0] = pack2(a0.x, a0.x); xa[1] = pack2(a0.y, a0.y);
    xa[2] = pack2(a0.z, a0.z); xa[3] = pack2(a0.w, a0.w);
    xa[4] = pack2(a1.x, a1.x); xa[5] = pack2(a1.y, a1.y);
    xa[6] = pack2(a1.z, a1.z); xa[7] = pack2(a1.w, a1.w);
    xb[0] = pack2(b0.x, b0.x); xb[1] = pack2(b0.y, b0.y);
    xb[2] = pack2(b0.z, b0.z); xb[3] = pack2(b0.w, b0.w);
    xb[4] = pack2(b1.x, b1.x); xb[5] = pack2(b1.y, b1.y);
    xb[6] = pack2(b1.z, b1.z); xb[7] = pack2(b1.w, b1.w);
    xc[0] = pack2(c0.x, c0.x); xc[1] = pack2(c0.y, c0.y);
    xc[2] = pack2(c0.z, c0.z); xc[3] = pack2(c0.w, c0.w);
    xc[4] = pack2(c1.x, c1.x); xc[5] = pack2(c1.y, c1.y);
    xc[6] = pack2(c1.z, c1.z); xc[7] = pack2(c1.w, c1.w);
    xd[0] = pack2(d0.x, d0.x); xd[1] = pack2(d0.y, d0.y);
    xd[2] = pack2(d0.z, d0.z); xd[3] = pack2(d0.w, d0.w);
    xd[4] = pack2(d1.x, d1.x); xd[5] = pack2(d1.y, d1.y);
    xd[6] = pack2(d1.z, d1.z); xd[7] = pack2(d1.w, d1.w);

    const u64 negone = pack2(-1.0f, -1.0f);
    float sa0 = 0.f, sa1 = 0.f, sb0 = 0.f, sb1 = 0.f;
    float sc0 = 0.f, sc1 = 0.f, sd0 = 0.f, sd1 = 0.f;

#pragma unroll
    for (int kp = 0; kp < KP; kp++) {
        const u64* w = sw + kp * SLOTS;
        u64 qa = 0ull, qb = 0ull, qc = 0ull, qd = 0ull;
        int idx = 0;
#pragma unroll
        for (int i = 0; i < DIM; i++) {
            u64 zi = w[idx++];
            u64 za = zi, zb = zi, zc = zi, zd = zi;
#pragma unroll
            for (int j = 0; j <= i; j++) {
                u64 p = w[idx++];
                za = ffma2(p, xa[j], za);
                zb = ffma2(p, xb[j], zb);
                zc = ffma2(p, xc[j], zc);
                zd = ffma2(p, xd[j], zd);
            }
            qa = ffma2(za, za, qa);
            qb = ffma2(zb, zb, qb);
            qc = ffma2(zc, zc, qc);
            qd = ffma2(zd, zd, qd);
        }
        u64 cc = w[44];
        u64 wa = ffma2(qa, negone, cc);
        u64 wb = ffma2(qb, negone, cc);
        u64 wc = ffma2(qc, negone, cc);
        u64 wd = ffma2(qd, negone, cc);
        float f0, f1;
        unpack2(wa, f0, f1); sa0 += ex2f(f0); sa1 += ex2f(f1);
        unpack2(wb, f0, f1); sb0 += ex2f(f0); sb1 += ex2f(f1);
        unpack2(wc, f0, f1); sc0 += ex2f(f0); sc1 += ex2f(f1);
        unpack2(wd, f0, f1); sd0 += ex2f(f0); sd1 += ex2f(f1);
    }

    const float M = sM;
    out[gid]                    = M + __logf(fmaxf(sa0 + sa1, 1e-37f));
    out[gid + (size_t)q]        = M + __logf(fmaxf(sb0 + sb1, 1e-37f));
    out[gid + 2 * (size_t)q]    = M + __logf(fmaxf(sc0 + sc1, 1e-37f));
    out[gid + 3 * (size_t)q]    = M + __logf(fmaxf(sd0 + sd1, 1e-37f));
}

extern "C" void kernel_launch(void* const* d_in, const int* in_sizes, int n_in,
                              void* d_out, int out_size) {
    const float* x     = (const float*)d_in[0];
    const float* pi    = (const float*)d_in[1];
    const float* means = (const float*)d_in[2];
    const float* cv    = (const float*)d_in[3];
    float* out = (float*)d_out;

    const int n = in_sizes[0] / 8;   // 524288
    const int q = n / 4;             // 131072 points per quarter

    gmm_fused<<<q / 128, 128>>>(x, pi, means, cv, out, q);
}